// round 3
// baseline (speedup 1.0000x reference)
#include <cuda_runtime.h>

// -------- problem constants (shapes fixed by the dataset) --------
#define MAXN 50000   // N_NODES
// D_NODE = 128, HID = 256, D_OUT = 256

// -------- scratch: __device__ globals (no allocations allowed) --------
__device__ float g_sums[MAXN * 256];  // scatter-sum of edge MLP outputs, [N,256]
__device__ int   g_cnt [MAXN];        // in-degree per node
__device__ int   g_idx64;             // 1 if edge_index buffer is int64, 0 if int32

// ======================================================================
// Kernel -1: detect index dtype.
// If int64 (little-endian), every odd 32-bit word is the high half of a
// value < 50000 -> 0. If int32, odd words are random node indices.
// ======================================================================
__global__ void detect_idx_kernel(const int* __restrict__ ei_raw) {
    __shared__ int any_nonzero;
    if (threadIdx.x == 0) any_nonzero = 0;
    __syncthreads();
    // first 1024 odd words are always within bounds for either dtype
    for (int i = threadIdx.x; i < 1024; i += blockDim.x)
        if (ei_raw[2 * i + 1] != 0) any_nonzero = 1;
    __syncthreads();
    if (threadIdx.x == 0) g_idx64 = (any_nonzero == 0) ? 1 : 0;
}

__device__ __forceinline__ int load_idx(const void* ei, long long pos, int nmax) {
    int v = g_idx64 ? (int)((const long long*)ei)[pos]
                    : ((const int*)ei)[pos];
    // defensive clamp: never fault on a bad index
    return min(max(v, 0), nmax - 1);
}

// ======================================================================
// Kernel 0: zero the scratch
// ======================================================================
__global__ void zero_kernel(int n_nodes) {
    int tid    = blockIdx.x * blockDim.x + threadIdx.x;
    int stride = gridDim.x * blockDim.x;
    int tot4 = n_nodes * 64;  // (n*256)/4
    float4* s4 = (float4*)g_sums;
    float4 z = make_float4(0.f, 0.f, 0.f, 0.f);
    for (int i = tid; i < tot4; i += stride) s4[i] = z;
    for (int i = tid; i < n_nodes; i += stride) g_cnt[i] = 0;
}

// ======================================================================
// Kernel 1: edge MLP (fused 2-layer) + atomic scatter-add + degree count
//   tile = 64 edges, 256 threads, each thread owns an 8x8 micro-tile.
//   smem: buf[64*256] input tile (later overwritten with H1),
//         wbuf[16*256] staged weight chunk.
// ======================================================================
__global__ __launch_bounds__(256, 2)
void edge_mlp_kernel(const float* __restrict__ x,
                     const void* __restrict__ edge_index,
                     const float* __restrict__ edge_attr,
                     const float* __restrict__ w1a, const float* __restrict__ b1a,
                     const float* __restrict__ w1b, const float* __restrict__ b1b,
                     int E, int N)
{
    extern __shared__ float smem[];
    float* buf  = smem;             // 64 * 256
    float* wbuf = smem + 64 * 256;  // 16 * 256
    __shared__ int srow[64];
    __shared__ int scol[64];

    const int tid = threadIdx.x;
    const int er  = tid >> 5;   // 0..7  (edge-row group: edges er*8 .. er*8+7)
    const int cg  = tid & 31;   // 0..31 (col group: cols cg*8 .. cg*8+7)
    const int e0  = blockIdx.x * 64;
    const int ecnt = min(64, E - e0);

    // stage row/col indices; count degrees
    if (tid < 64) {
        int r = -1, c = -1;
        if (tid < ecnt) {
            r = load_idx(edge_index, (long long)(e0 + tid), N);
            c = load_idx(edge_index, (long long)E + e0 + tid, N);
            atomicAdd(&g_cnt[c], 1);
        }
        srow[tid] = r;
        scol[tid] = c;
    }
    __syncthreads();

    // gather input tile: [e][0:128) = x[row[e]], [e][128:256) = edge_attr[e]
    for (int idx = tid; idx < 64 * 32; idx += 256) {
        int e = idx >> 5, c4 = idx & 31;
        float4 v = make_float4(0.f, 0.f, 0.f, 0.f);
        if (e < ecnt) {
            long long r = srow[e];
            v = *(const float4*)(x + r * 128 + c4 * 4);
        }
        *(float4*)(buf + e * 256 + c4 * 4) = v;
    }
    for (int idx = tid; idx < 64 * 32; idx += 256) {
        int e = idx >> 5, c4 = idx & 31;
        float4 v = make_float4(0.f, 0.f, 0.f, 0.f);
        if (e < ecnt)
            v = *(const float4*)(edge_attr + (long long)(e0 + e) * 128 + c4 * 4);
        *(float4*)(buf + e * 256 + 128 + c4 * 4) = v;
    }

    float acc[8][8];
    #pragma unroll
    for (int i = 0; i < 8; i++)
        #pragma unroll
        for (int j = 0; j < 8; j++) acc[i][j] = 0.f;

    // ---- GEMM1: H1 = buf(64x256) @ w1a(256x256) ----
    for (int k0 = 0; k0 < 256; k0 += 16) {
        __syncthreads();  // previous chunk consumed (also covers initial tile load)
        const float4* wsrc = (const float4*)(w1a + k0 * 256);
        float4* wd = (float4*)wbuf;
        #pragma unroll
        for (int t = 0; t < 4; t++) wd[tid + t * 256] = wsrc[tid + t * 256];
        __syncthreads();
        #pragma unroll
        for (int kk = 0; kk < 16; kk++) {
            float a[8];
            #pragma unroll
            for (int i = 0; i < 8; i++)
                a[i] = buf[(er * 8 + i) * 256 + k0 + kk];   // warp-broadcast
            float4 b0 = *(float4*)(wbuf + kk * 256 + cg * 8);
            float4 b1 = *(float4*)(wbuf + kk * 256 + cg * 8 + 4);
            float b[8] = {b0.x, b0.y, b0.z, b0.w, b1.x, b1.y, b1.z, b1.w};
            #pragma unroll
            for (int i = 0; i < 8; i++)
                #pragma unroll
                for (int j = 0; j < 8; j++)
                    acc[i][j] = fmaf(a[i], b[j], acc[i][j]);
        }
    }

    // bias + ELU, write H1 over buf (input tile fully consumed)
    __syncthreads();
    {
        float bj[8];
        #pragma unroll
        for (int j = 0; j < 8; j++) bj[j] = b1a[cg * 8 + j];
        #pragma unroll
        for (int i = 0; i < 8; i++) {
            float vv[8];
            #pragma unroll
            for (int j = 0; j < 8; j++) {
                float v = acc[i][j] + bj[j];
                vv[j] = (v > 0.f) ? v : expm1f(v);
                acc[i][j] = 0.f;
            }
            *(float4*)(buf + (er * 8 + i) * 256 + cg * 8)     = make_float4(vv[0], vv[1], vv[2], vv[3]);
            *(float4*)(buf + (er * 8 + i) * 256 + cg * 8 + 4) = make_float4(vv[4], vv[5], vv[6], vv[7]);
        }
    }

    // ---- GEMM2: H = H1(64x256) @ w1b(256x256) ----
    for (int k0 = 0; k0 < 256; k0 += 16) {
        __syncthreads();
        const float4* wsrc = (const float4*)(w1b + k0 * 256);
        float4* wd = (float4*)wbuf;
        #pragma unroll
        for (int t = 0; t < 4; t++) wd[tid + t * 256] = wsrc[tid + t * 256];
        __syncthreads();
        #pragma unroll
        for (int kk = 0; kk < 16; kk++) {
            float a[8];
            #pragma unroll
            for (int i = 0; i < 8; i++)
                a[i] = buf[(er * 8 + i) * 256 + k0 + kk];
            float4 b0 = *(float4*)(wbuf + kk * 256 + cg * 8);
            float4 b1 = *(float4*)(wbuf + kk * 256 + cg * 8 + 4);
            float b[8] = {b0.x, b0.y, b0.z, b0.w, b1.x, b1.y, b1.z, b1.w};
            #pragma unroll
            for (int i = 0; i < 8; i++)
                #pragma unroll
                for (int j = 0; j < 8; j++)
                    acc[i][j] = fmaf(a[i], b[j], acc[i][j]);
        }
    }

    // epilogue: bias + atomic scatter-add into g_sums[col[e]]
    {
        float bj[8];
        #pragma unroll
        for (int j = 0; j < 8; j++) bj[j] = b1b[cg * 8 + j];
        #pragma unroll
        for (int i = 0; i < 8; i++) {
            int c = scol[er * 8 + i];
            if (c >= 0) {
                float* dst = g_sums + (long long)c * 256 + cg * 8;
                #pragma unroll
                for (int j = 0; j < 8; j++)
                    atomicAdd(dst + j, acc[i][j] + bj[j]);
            }
        }
    }
}

// ======================================================================
// Kernel 2: node MLP (fused 2-layer), z = [x | mean] (64x384 tile)
// ======================================================================
__global__ __launch_bounds__(256)
void node_mlp_kernel(const float* __restrict__ x,
                     const float* __restrict__ w2a, const float* __restrict__ b2a,
                     const float* __restrict__ w2b, const float* __restrict__ b2b,
                     float* __restrict__ out, int N)
{
    extern __shared__ float smem[];
    float* buf  = smem;             // 64 * 384 (z tile; first 64*256 reused for H1)
    float* wbuf = smem + 64 * 384;  // 16 * 256
    __shared__ float sInv[64];

    const int tid = threadIdx.x;
    const int er  = tid >> 5;
    const int cg  = tid & 31;
    const int n0  = blockIdx.x * 64;
    const int ncnt = min(64, N - n0);

    if (tid < 64) {
        float inv = 0.f;
        if (tid < ncnt) {
            int c = g_cnt[n0 + tid];
            inv = 1.0f / (float)max(c, 1);
        }
        sInv[tid] = inv;
    }
    __syncthreads();

    // z[:, 0:128) = x
    for (int idx = tid; idx < 64 * 32; idx += 256) {
        int e = idx >> 5, c4 = idx & 31;
        float4 v = make_float4(0.f, 0.f, 0.f, 0.f);
        if (e < ncnt) v = *(const float4*)(x + (long long)(n0 + e) * 128 + c4 * 4);
        *(float4*)(buf + e * 384 + c4 * 4) = v;
    }
    // z[:, 128:384) = mean = sums * inv
    for (int idx = tid; idx < 64 * 64; idx += 256) {
        int e = idx >> 6, c4 = idx & 63;
        float4 v = make_float4(0.f, 0.f, 0.f, 0.f);
        if (e < ncnt) {
            v = *(const float4*)(g_sums + (long long)(n0 + e) * 256 + c4 * 4);
            float inv = sInv[e];
            v.x *= inv; v.y *= inv; v.z *= inv; v.w *= inv;
        }
        *(float4*)(buf + e * 384 + 128 + c4 * 4) = v;
    }

    float acc[8][8];
    #pragma unroll
    for (int i = 0; i < 8; i++)
        #pragma unroll
        for (int j = 0; j < 8; j++) acc[i][j] = 0.f;

    // ---- GEMM1: H1 = z(64x384) @ w2a(384x256) ----
    for (int k0 = 0; k0 < 384; k0 += 16) {
        __syncthreads();
        const float4* wsrc = (const float4*)(w2a + k0 * 256);
        float4* wd = (float4*)wbuf;
        #pragma unroll
        for (int t = 0; t < 4; t++) wd[tid + t * 256] = wsrc[tid + t * 256];
        __syncthreads();
        #pragma unroll
        for (int kk = 0; kk < 16; kk++) {
            float a[8];
            #pragma unroll
            for (int i = 0; i < 8; i++)
                a[i] = buf[(er * 8 + i) * 384 + k0 + kk];
            float4 b0 = *(float4*)(wbuf + kk * 256 + cg * 8);
            float4 b1 = *(float4*)(wbuf + kk * 256 + cg * 8 + 4);
            float b[8] = {b0.x, b0.y, b0.z, b0.w, b1.x, b1.y, b1.z, b1.w};
            #pragma unroll
            for (int i = 0; i < 8; i++)
                #pragma unroll
                for (int j = 0; j < 8; j++)
                    acc[i][j] = fmaf(a[i], b[j], acc[i][j]);
        }
    }

    // bias + ELU, write H1 (row stride 256) over buf
    __syncthreads();
    {
        float bj[8];
        #pragma unroll
        for (int j = 0; j < 8; j++) bj[j] = b2a[cg * 8 + j];
        #pragma unroll
        for (int i = 0; i < 8; i++) {
            float vv[8];
            #pragma unroll
            for (int j = 0; j < 8; j++) {
                float v = acc[i][j] + bj[j];
                vv[j] = (v > 0.f) ? v : expm1f(v);
                acc[i][j] = 0.f;
            }
            *(float4*)(buf + (er * 8 + i) * 256 + cg * 8)     = make_float4(vv[0], vv[1], vv[2], vv[3]);
            *(float4*)(buf + (er * 8 + i) * 256 + cg * 8 + 4) = make_float4(vv[4], vv[5], vv[6], vv[7]);
        }
    }

    // ---- GEMM2: out = H1(64x256) @ w2b(256x256) + b2b ----
    for (int k0 = 0; k0 < 256; k0 += 16) {
        __syncthreads();
        const float4* wsrc = (const float4*)(w2b + k0 * 256);
        float4* wd = (float4*)wbuf;
        #pragma unroll
        for (int t = 0; t < 4; t++) wd[tid + t * 256] = wsrc[tid + t * 256];
        __syncthreads();
        #pragma unroll
        for (int kk = 0; kk < 16; kk++) {
            float a[8];
            #pragma unroll
            for (int i = 0; i < 8; i++)
                a[i] = buf[(er * 8 + i) * 256 + k0 + kk];
            float4 b0 = *(float4*)(wbuf + kk * 256 + cg * 8);
            float4 b1 = *(float4*)(wbuf + kk * 256 + cg * 8 + 4);
            float b[8] = {b0.x, b0.y, b0.z, b0.w, b1.x, b1.y, b1.z, b1.w};
            #pragma unroll
            for (int i = 0; i < 8; i++)
                #pragma unroll
                for (int j = 0; j < 8; j++)
                    acc[i][j] = fmaf(a[i], b[j], acc[i][j]);
        }
    }

    {
        float bj[8];
        #pragma unroll
        for (int j = 0; j < 8; j++) bj[j] = b2b[cg * 8 + j];
        #pragma unroll
        for (int i = 0; i < 8; i++) {
            int n = n0 + er * 8 + i;
            if (n < N) {
                float vv[8];
                #pragma unroll
                for (int j = 0; j < 8; j++) vv[j] = acc[i][j] + bj[j];
                *(float4*)(out + (long long)n * 256 + cg * 8)     = make_float4(vv[0], vv[1], vv[2], vv[3]);
                *(float4*)(out + (long long)n * 256 + cg * 8 + 4) = make_float4(vv[4], vv[5], vv[6], vv[7]);
            }
        }
    }
}

// ======================================================================
// launch
// ======================================================================
extern "C" void kernel_launch(void* const* d_in, const int* in_sizes, int n_in,
                              void* d_out, int out_size)
{
    const float* x  = (const float*)d_in[0];
    const void*  ei = d_in[1];                 // int32 or int64 [2, E] — auto-detected
    const float* ea = (const float*)d_in[2];
    // d_in[3] = u (unused), d_in[4] = batch (unused)
    const float* w1a = (const float*)d_in[5];
    const float* b1a = (const float*)d_in[6];
    const float* w1b = (const float*)d_in[7];
    const float* b1b = (const float*)d_in[8];
    const float* w2a = (const float*)d_in[9];
    const float* b2a = (const float*)d_in[10];
    const float* w2b = (const float*)d_in[11];
    const float* b2b = (const float*)d_in[12];
    float* out = (float*)d_out;

    const int N = in_sizes[0] / 128;
    const int E = in_sizes[1] / 2;

    const int EDGE_SMEM = (64 * 256 + 16 * 256) * 4;  // 81920
    const int NODE_SMEM = (64 * 384 + 16 * 256) * 4;  // 114688
    cudaFuncSetAttribute(edge_mlp_kernel, cudaFuncAttributeMaxDynamicSharedMemorySize, EDGE_SMEM);
    cudaFuncSetAttribute(node_mlp_kernel, cudaFuncAttributeMaxDynamicSharedMemorySize, NODE_SMEM);

    detect_idx_kernel<<<1, 256>>>((const int*)ei);
    zero_kernel<<<1024, 256>>>(N);
    edge_mlp_kernel<<<(E + 63) / 64, 256, EDGE_SMEM>>>(x, ei, ea, w1a, b1a, w1b, b1b, E, N);
    node_mlp_kernel<<<(N + 63) / 64, 256, NODE_SMEM>>>(x, w2a, b2a, w2b, b2b, out, N);
}